// round 12
// baseline (speedup 1.0000x reference)
#include <cuda_runtime.h>
#include <cuda_fp16.h>
#include <stdint.h>

// Fixed problem shapes
#define NLAT_IN   181
#define NLON_IN   360
#define NLAT_OUT  361
#define NLON_OUT  720
#define KSIZE     3
#define CIN       16
#define COUT      16
#define NNZ_MAX   8192

#define NPTS        (NLAT_IN * NLON_IN)          // 65160
#define NPT4        (NPTS / 4)                   // 16290 point-quads
#define NRINGS      (KSIZE * NLAT_IN)            // 543
#define RING_W      (2 * NLON_IN)                // 720 (ring duplicated along lon)
#define PLANE_D     (NRINGS * RING_W)            // 390960 uint4 per plane
#define NBINS       (NLAT_OUT * 2)               // 722 (lat, parity) segments
#define SCAN_P      768
#define ENT_MAX     12288
#define SE_CAP      160

#define NBLOCKS     444                          // 148 SMs x 3 blocks, co-resident
#define EIN_CHUNKS  43                           // ceil(NPT4 / 384)
#define EIN_UNITS   (6 * EIN_CHUNKS)             // 258 (k x cg x chunk)
#define CNT_BLOCKS  22                           // 22 x 384 >= 8192
#define CNT_BASE    EIN_UNITS                    // 258..279
#define SCAN_BID    (EIN_UNITS + CNT_BLOCKS)     // 280
#define MASTER_TGT  (EIN_UNITS + CNT_BLOCKS)
#define GUNITS      (NLAT_OUT * 2)               // 722 gather units (ho, cg)

// Scratch (device globals — zero-initialized at load; no dynamic allocation)
__device__ uint4 g_xwd[2][PLANE_D];     // ring-duplicated fp16-packed xw (12.5 MB)
__device__ int   g_count[NBINS];
__device__ int   g_starts[NBINS + 2];
__device__ int   g_cursor[NBINS];
__device__ int2  g_entries[ENT_MAX];    // .x = ring*720 + (360-shift) ; .y = half2(v,v)
                                        // pad slots stay all-zero (v=0; addr t is in-bounds)
__device__ unsigned g_cntA = 0;
__device__ unsigned g_scanflag = 0;
__device__ unsigned g_master = 0;
__device__ unsigned g_work = 0;
__device__ unsigned g_exit = 0;

__device__ __forceinline__ unsigned vld(unsigned* p) {
    return *((volatile unsigned*)p);
}

// 4-entry batch; entries from SMEM; address = e.x + t (no wrap, no decode).
__device__ __forceinline__ void batch4_s(const int2* ep, int i, int t,
                                         const uint4* __restrict__ plane, float* acc)
{
    const __half2 hz = __float2half2_rn(0.0f);
    int2 e0 = ep[i + 0];
    int2 e1 = ep[i + 1];
    int2 e2 = ep[i + 2];
    int2 e3 = ep[i + 3];
    uint4 u0 = __ldg(&plane[e0.x + t]);
    uint4 u1 = __ldg(&plane[e1.x + t]);
    uint4 u2 = __ldg(&plane[e2.x + t]);
    uint4 u3 = __ldg(&plane[e3.x + t]);
    __half2 v0 = *(__half2*)&e0.y;
    __half2 v1 = *(__half2*)&e1.y;
    __half2 v2 = *(__half2*)&e2.y;
    __half2 v3 = *(__half2*)&e3.y;
    __half2 h0 = hz, h1 = hz, h2 = hz, h3 = hz;
    h0 = __hfma2(v0, *(__half2*)&u0.x, h0);  h1 = __hfma2(v0, *(__half2*)&u0.y, h1);
    h2 = __hfma2(v0, *(__half2*)&u0.z, h2);  h3 = __hfma2(v0, *(__half2*)&u0.w, h3);
    h0 = __hfma2(v1, *(__half2*)&u1.x, h0);  h1 = __hfma2(v1, *(__half2*)&u1.y, h1);
    h2 = __hfma2(v1, *(__half2*)&u1.z, h2);  h3 = __hfma2(v1, *(__half2*)&u1.w, h3);
    h0 = __hfma2(v2, *(__half2*)&u2.x, h0);  h1 = __hfma2(v2, *(__half2*)&u2.y, h1);
    h2 = __hfma2(v2, *(__half2*)&u2.z, h2);  h3 = __hfma2(v2, *(__half2*)&u2.w, h3);
    h0 = __hfma2(v3, *(__half2*)&u3.x, h0);  h1 = __hfma2(v3, *(__half2*)&u3.y, h1);
    h2 = __hfma2(v3, *(__half2*)&u3.z, h2);  h3 = __hfma2(v3, *(__half2*)&u3.w, h3);
    float2 f;
    f = __half22float2(h0); acc[0] += f.x; acc[1] += f.y;
    f = __half22float2(h1); acc[2] += f.x; acc[3] += f.y;
    f = __half22float2(h2); acc[4] += f.x; acc[5] += f.y;
    f = __half22float2(h3); acc[6] += f.x; acc[7] += f.y;
}

// Global-memory fallback variant.
__device__ __forceinline__ void batch4_g(const int2* __restrict__ ep, int i, int t,
                                         const uint4* __restrict__ plane, float* acc)
{
    const __half2 hz = __float2half2_rn(0.0f);
    int2 e0 = __ldg(&ep[i + 0]);
    int2 e1 = __ldg(&ep[i + 1]);
    int2 e2 = __ldg(&ep[i + 2]);
    int2 e3 = __ldg(&ep[i + 3]);
    uint4 u0 = __ldg(&plane[e0.x + t]);
    uint4 u1 = __ldg(&plane[e1.x + t]);
    uint4 u2 = __ldg(&plane[e2.x + t]);
    uint4 u3 = __ldg(&plane[e3.x + t]);
    __half2 v0 = *(__half2*)&e0.y;
    __half2 v1 = *(__half2*)&e1.y;
    __half2 v2 = *(__half2*)&e2.y;
    __half2 v3 = *(__half2*)&e3.y;
    __half2 h0 = hz, h1 = hz, h2 = hz, h3 = hz;
    h0 = __hfma2(v0, *(__half2*)&u0.x, h0);  h1 = __hfma2(v0, *(__half2*)&u0.y, h1);
    h2 = __hfma2(v0, *(__half2*)&u0.z, h2);  h3 = __hfma2(v0, *(__half2*)&u0.w, h3);
    h0 = __hfma2(v1, *(__half2*)&u1.x, h0);  h1 = __hfma2(v1, *(__half2*)&u1.y, h1);
    h2 = __hfma2(v1, *(__half2*)&u1.z, h2);  h3 = __hfma2(v1, *(__half2*)&u1.w, h3);
    h0 = __hfma2(v2, *(__half2*)&u2.x, h0);  h1 = __hfma2(v2, *(__half2*)&u2.y, h1);
    h2 = __hfma2(v2, *(__half2*)&u2.z, h2);  h3 = __hfma2(v2, *(__half2*)&u2.w, h3);
    h0 = __hfma2(v3, *(__half2*)&u3.x, h0);  h1 = __hfma2(v3, *(__half2*)&u3.y, h1);
    h2 = __hfma2(v3, *(__half2*)&u3.z, h2);  h3 = __hfma2(v3, *(__half2*)&u3.w, h3);
    float2 f;
    f = __half22float2(h0); acc[0] += f.x; acc[1] += f.y;
    f = __half22float2(h1); acc[2] += f.x; acc[3] += f.y;
    f = __half22float2(h2); acc[4] += f.x; acc[5] += f.y;
    f = __half22float2(h3); acc[6] += f.x; acc[7] += f.y;
}

// ---------------------------------------------------------------------------
// One persistent kernel: 444 blocks, all co-resident (3/SM forced).
__global__ __launch_bounds__(384, 3) void fused_kernel(
    const float* __restrict__ x, const float* __restrict__ weight,
    const int* __restrict__ ker_idx, const int* __restrict__ row_idx,
    const int* __restrict__ col_idx, const float* __restrict__ vals,
    const float* __restrict__ bias, float* __restrict__ out, int nnz)
{
    const int b  = blockIdx.x;
    const int t  = threadIdx.x;
    const int nt = blockDim.x;   // 384

    __shared__ int s_arena[2 * SCAN_P + NBINS];
    __shared__ int s_u;

    // ======================= PHASE A =======================
    if (b < EIN_UNITS) {
        // ---- einsum: (k, cg); thread = 4 points, 8 channels; duplicated store ----
        const int v     = b / EIN_CHUNKS;
        const int chunk = b - v * EIN_CHUNKS;
        const int k     = v >> 1;
        const int cg    = v & 1;

        __shared__ float sw[128];
        if (t < 128) {
            int cc = t >> 4, ci = t & 15;
            sw[((cc >> 2) * 16 + ci) * 4 + (cc & 3)] =
                weight[((cg * 8 + cc) * CIN + ci) * KSIZE + k];
        }
        __syncthreads();

        const int g = chunk * 384 + t;
        if (g < NPT4) {
            const float4* __restrict__ x4 = (const float4*)x;
            const float4* __restrict__ w4 = (const float4*)sw;

            float4 acc[8];
            #pragma unroll
            for (int c = 0; c < 8; c++) acc[c] = make_float4(0.f, 0.f, 0.f, 0.f);

            #pragma unroll
            for (int ci = 0; ci < CIN; ci++) {
                float4 xv  = __ldg(&x4[ci * NPT4 + g]);
                float4 wlo = w4[ci];
                float4 whi = w4[16 + ci];
                acc[0].x = fmaf(wlo.x, xv.x, acc[0].x); acc[0].y = fmaf(wlo.x, xv.y, acc[0].y);
                acc[0].z = fmaf(wlo.x, xv.z, acc[0].z); acc[0].w = fmaf(wlo.x, xv.w, acc[0].w);
                acc[1].x = fmaf(wlo.y, xv.x, acc[1].x); acc[1].y = fmaf(wlo.y, xv.y, acc[1].y);
                acc[1].z = fmaf(wlo.y, xv.z, acc[1].z); acc[1].w = fmaf(wlo.y, xv.w, acc[1].w);
                acc[2].x = fmaf(wlo.z, xv.x, acc[2].x); acc[2].y = fmaf(wlo.z, xv.y, acc[2].y);
                acc[2].z = fmaf(wlo.z, xv.z, acc[2].z); acc[2].w = fmaf(wlo.z, xv.w, acc[2].w);
                acc[3].x = fmaf(wlo.w, xv.x, acc[3].x); acc[3].y = fmaf(wlo.w, xv.y, acc[3].y);
                acc[3].z = fmaf(wlo.w, xv.z, acc[3].z); acc[3].w = fmaf(wlo.w, xv.w, acc[3].w);
                acc[4].x = fmaf(whi.x, xv.x, acc[4].x); acc[4].y = fmaf(whi.x, xv.y, acc[4].y);
                acc[4].z = fmaf(whi.x, xv.z, acc[4].z); acc[4].w = fmaf(whi.x, xv.w, acc[4].w);
                acc[5].x = fmaf(whi.y, xv.x, acc[5].x); acc[5].y = fmaf(whi.y, xv.y, acc[5].y);
                acc[5].z = fmaf(whi.y, xv.z, acc[5].z); acc[5].w = fmaf(whi.y, xv.w, acc[5].w);
                acc[6].x = fmaf(whi.z, xv.x, acc[6].x); acc[6].y = fmaf(whi.z, xv.y, acc[6].y);
                acc[6].z = fmaf(whi.z, xv.z, acc[6].z); acc[6].w = fmaf(whi.z, xv.w, acc[6].w);
                acc[7].x = fmaf(whi.w, xv.x, acc[7].x); acc[7].y = fmaf(whi.w, xv.y, acc[7].y);
                acc[7].z = fmaf(whi.w, xv.z, acc[7].z); acc[7].w = fmaf(whi.w, xv.w, acc[7].w);
            }

            const int g4   = g * 4;
            const int tin  = g4 / NLON_IN;           // latitude within plane
            const int po   = g4 - tin * NLON_IN;     // 0..356, multiple of 4
            uint4* __restrict__ dst =
                &g_xwd[cg][(k * NLAT_IN + tin) * RING_W + po];

            uint4 u0, u1, u2, u3;
            {
                __half2 h01 = __floats2half2_rn(acc[0].x, acc[1].x);
                __half2 h23 = __floats2half2_rn(acc[2].x, acc[3].x);
                __half2 h45 = __floats2half2_rn(acc[4].x, acc[5].x);
                __half2 h67 = __floats2half2_rn(acc[6].x, acc[7].x);
                u0 = make_uint4(*(unsigned*)&h01, *(unsigned*)&h23,
                                *(unsigned*)&h45, *(unsigned*)&h67);
            }
            {
                __half2 h01 = __floats2half2_rn(acc[0].y, acc[1].y);
                __half2 h23 = __floats2half2_rn(acc[2].y, acc[3].y);
                __half2 h45 = __floats2half2_rn(acc[4].y, acc[5].y);
                __half2 h67 = __floats2half2_rn(acc[6].y, acc[7].y);
                u1 = make_uint4(*(unsigned*)&h01, *(unsigned*)&h23,
                                *(unsigned*)&h45, *(unsigned*)&h67);
            }
            {
                __half2 h01 = __floats2half2_rn(acc[0].z, acc[1].z);
                __half2 h23 = __floats2half2_rn(acc[2].z, acc[3].z);
                __half2 h45 = __floats2half2_rn(acc[4].z, acc[5].z);
                __half2 h67 = __floats2half2_rn(acc[6].z, acc[7].z);
                u2 = make_uint4(*(unsigned*)&h01, *(unsigned*)&h23,
                                *(unsigned*)&h45, *(unsigned*)&h67);
            }
            {
                __half2 h01 = __floats2half2_rn(acc[0].w, acc[1].w);
                __half2 h23 = __floats2half2_rn(acc[2].w, acc[3].w);
                __half2 h45 = __floats2half2_rn(acc[4].w, acc[5].w);
                __half2 h67 = __floats2half2_rn(acc[6].w, acc[7].w);
                u3 = make_uint4(*(unsigned*)&h01, *(unsigned*)&h23,
                                *(unsigned*)&h45, *(unsigned*)&h67);
            }
            dst[0] = u0; dst[1] = u1; dst[2] = u2; dst[3] = u3;
            dst[NLON_IN + 0] = u0; dst[NLON_IN + 1] = u1;      // duplicated copy
            dst[NLON_IN + 2] = u2; dst[NLON_IN + 3] = u3;
        }
        __threadfence();
        __syncthreads();
        if (t == 0) atomicAdd(&g_master, 1u);
    }
    else if (b < SCAN_BID) {
        // ---- count block: histogram my slice, then wait & scatter ----
        const int slice = b - CNT_BASE;
        const int i = slice * nt + t;
        int col = 0, hi = 0, p = 0;
        bool valid = (i < nnz);
        if (valid) {
            col = col_idx[i];
            hi  = col / NLON_OUT;
            p   = col - hi * NLON_OUT;
            atomicAdd(&g_count[hi * 2 + (p & 1)], 1);
        }
        __threadfence();
        __syncthreads();
        if (t == 0) atomicAdd(&g_cntA, 1u);

        if (t == 0) { while (vld(&g_scanflag) == 0u) __nanosleep(128); }
        __syncthreads();
        __threadfence();

        // zero my stripe of g_count for the next graph replay
        if (t < 33) {
            int bin = slice * 33 + t;
            if (bin < NBINS) g_count[bin] = 0;
        }

        if (valid) {
            int key = hi * 2 + (p & 1);
            int pos = atomicAdd(&g_cursor[key], 1);
            // precomputed un-wrapped base: ring*720 + (360 - shift)
            int base2 = (ker_idx[i] * NLAT_IN + row_idx[i]) * RING_W
                        + NLON_IN - (p >> 1);
            __half2 vh = __float2half2_rn(vals[i]);
            g_entries[pos] = make_int2(base2, (int)*(unsigned*)&vh);
        }
        __threadfence();
        __syncthreads();
        if (t == 0) atomicAdd(&g_master, 1u);
    }
    else if (b == SCAN_BID) {
        // ---- scanner: wait counts, pad to x4, scan, publish ----
        if (t == 0) { while (vld(&g_cntA) < CNT_BLOCKS) __nanosleep(128); }
        __syncthreads();
        __threadfence();

        int* bufA = s_arena;
        int* bufB = s_arena + SCAN_P;
        int* scnt = s_arena + 2 * SCAN_P;

        for (int i = t; i < SCAN_P; i += nt) {
            int c = (i < NBINS) ? g_count[i] : 0;
            int c4 = (c + 3) & ~3;
            bufA[i] = c4;
            if (i < NBINS) scnt[i] = c4;
        }
        __syncthreads();
        int* src = bufA; int* dst = bufB;
        for (int off = 1; off < SCAN_P; off <<= 1) {
            for (int i = t; i < SCAN_P; i += nt) {
                int vv = src[i];
                if (i >= off) vv += src[i - off];
                dst[i] = vv;
            }
            __syncthreads();
            int* tmp = src; src = dst; dst = tmp;
        }
        for (int i = t; i < NBINS; i += nt) {
            g_starts[i + 1] = src[i];
            g_cursor[i]     = src[i] - scnt[i];
        }
        if (t == 0) g_starts[0] = 0;
        __threadfence();
        __syncthreads();
        if (t == 0) atomicExch(&g_scanflag, 1u);
    }
    // blocks >= 281 fall straight through to the barrier

    // ======================= BARRIER =======================
    if (t == 0) { while (vld(&g_master) < MASTER_TGT) __nanosleep(128); }
    __syncthreads();
    __threadfence();

    // ======================= PHASE B: work-stealing gather =======================
    int2* se = (int2*)s_arena;

    while (true) {
        __syncthreads();
        if (t == 0) s_u = (int)atomicAdd(&g_work, 1u);
        __syncthreads();
        const int u = s_u;
        if (u >= GUNITS) break;

        const int ho = u >> 1;
        const int cg = u & 1;

        const int s0 = __ldg(&g_starts[2 * ho]);
        const int s1 = __ldg(&g_starts[2 * ho + 1]);
        const int s2 = __ldg(&g_starts[2 * ho + 2]);
        const int n4 = s2 - s0;
        const bool fits = (n4 <= SE_CAP);

        if (fits) {
            for (int i = t; i < n4; i += nt) se[i] = g_entries[s0 + i];
        }
        __syncthreads();

        if (t >= NLON_IN) continue;

        const uint4* __restrict__ plane = g_xwd[cg];
        const int nE4 = s1 - s0;
        const int nO4 = s2 - s1;

        float aE[8], aO[8];
        #pragma unroll
        for (int c = 0; c < 8; c++) { aE[c] = 0.0f; aO[c] = 0.0f; }

        if (fits) {
            int jE = 0, jO = 0;
            int jm = (nE4 > nO4) ? nE4 : nO4;
            for (int j = 0; j < jm; j += 4) {
                if (jE < nE4) { batch4_s(se, jE, t, plane, aE); jE += 4; }
                if (jO < nO4) { batch4_s(se + nE4, jO, t, plane, aO); jO += 4; }
            }
        } else {
            for (int i = 0; i < nE4; i += 4) batch4_g(&g_entries[s0], i, t, plane, aE);
            for (int i = 0; i < nO4; i += 4) batch4_g(&g_entries[s1], i, t, plane, aO);
        }

        #pragma unroll
        for (int c = 0; c < 8; c++) {
            int co = cg * 8 + c;
            float bb = __ldg(&bias[co]);
            float2* row = (float2*)(out + (size_t)co * (NLAT_OUT * NLON_OUT)
                                    + ho * NLON_OUT);
            row[t] = make_float2(aE[c] + bb, aO[c] + bb);
        }
    }

    // ======================= EXIT: last block resets state =======================
    __syncthreads();
    if (t == 0) {
        unsigned e = atomicAdd(&g_exit, 1u);
        if (e == NBLOCKS - 1) {
            g_master = 0u;
            g_cntA = 0u;
            g_scanflag = 0u;
            g_work = 0u;
            __threadfence();
            g_exit = 0u;
        }
    }
}

// ---------------------------------------------------------------------------
extern "C" void kernel_launch(void* const* d_in, const int* in_sizes, int n_in,
                              void* d_out, int out_size) {
    const float* x       = (const float*)d_in[0];
    const float* weight  = (const float*)d_in[1];
    const float* bias    = (const float*)d_in[2];
    const int*   ker_idx = (const int*)d_in[3];
    const int*   row_idx = (const int*)d_in[4];
    const int*   col_idx = (const int*)d_in[5];
    const float* vals    = (const float*)d_in[6];
    float* out = (float*)d_out;

    int nnz = in_sizes[3];
    if (nnz > NNZ_MAX) nnz = NNZ_MAX;

    fused_kernel<<<NBLOCKS, 384>>>(x, weight, ker_idx, row_idx, col_idx, vals,
                                   bias, out, nnz);
}